// round 9
// baseline (speedup 1.0000x reference)
#include <cuda_runtime.h>
#include <mma.h>
#include <cstdint>

using namespace nvcuda;

#define BB 8
#define DD 512
#define KK 32
#define NN 16384

// 16 MB scratch for soft-assign matrix A[b][n][k] (tf32-rounded by K1)
__device__ float A_buf[(size_t)BB * NN * KK];

// ============================================================================
// Kernel 1: A = softmax_k( s_k * (||x||^2 - 2 x.c_k + ||c_k||^2) )
//   (unchanged from R7 passing version)
// ============================================================================
#define T1N   256
#define T1DC  64
#define NCH   (DD/T1DC)       // 8
#define TILES 4
#define X1LD 264
#define X1F  (T1DC*X1LD)
#define C1LD 516
#define C1F  (KK*C1LD)
#define AS1LD 36
#define SM1_FLOATS (2*X1F + C1F + 64)
#define SM1_BYTES  (SM1_FLOATS*4)

__global__ __launch_bounds__(512, 1)
void k1_assign(const float* __restrict__ X,
               const float* __restrict__ CW,
               const float* __restrict__ scale)
{
    extern __shared__ float sm[];
    float* Xs0 = sm;
    float* Xs1 = Xs0 + X1F;
    float* Cs  = Xs1 + X1F;
    float* c2s = Cs + C1F;
    float* scs = c2s + 32;
    float* As  = Xs0;
    float* As2 = Xs1;
    float* x2p = Xs1 + 9216;

    const int t = threadIdx.x;
    const int w = t >> 5;
    const int b = blockIdx.y;
    const int tile_base = blockIdx.x * TILES;
    const float* Xb = X + (size_t)b * DD * NN;

    const int j  = t & 63;
    const int dr = t >> 6;
    const int nc = w & 7, half = w >> 3;

    float4 R[8];
    {
        const float* g = Xb + (size_t)dr * NN + tile_base * T1N + j * 4;
        #pragma unroll
        for (int r = 0; r < 8; ++r)
            R[r] = *(const float4*)(g + (size_t)(r * 8) * NN);
    }

    for (int i = t; i < KK * DD; i += 512) {
        int k = i >> 9, d = i & 511;
        Cs[k * C1LD + d] = wmma::__float_to_tf32(CW[i]);
    }
    if (t < 32) scs[t] = scale[t];
    __syncthreads();
    if (t < 32) {
        float s = 0.f;
        #pragma unroll 8
        for (int d = 0; d < DD; ++d) { float v = Cs[t * C1LD + d]; s += v * v; }
        c2s[t] = s;
    }

    wmma::fragment<wmma::accumulator, 16, 16, 8, float> p00, p01, p10, p11;
    wmma::fill_fragment(p00, 0.f); wmma::fill_fragment(p01, 0.f);
    wmma::fill_fragment(p10, 0.f); wmma::fill_fragment(p11, 0.f);
    float xa = 0.f, xb2 = 0.f, xc = 0.f, xd2 = 0.f;

    for (int u = 0; u < TILES * NCH; ++u) {
        const int c = u & 7;
        float* Xt = (u & 1) ? Xs1 : Xs0;

        #pragma unroll
        for (int r = 0; r < 8; ++r) {
            float4 v = R[r];
            xa += v.x * v.x; xb2 += v.y * v.y; xc += v.z * v.z; xd2 += v.w * v.w;
            v.x = wmma::__float_to_tf32(v.x);
            v.y = wmma::__float_to_tf32(v.y);
            v.z = wmma::__float_to_tf32(v.z);
            v.w = wmma::__float_to_tf32(v.w);
            *(float4*)&Xt[(r * 8 + dr) * X1LD + j * 4] = v;
        }
        if (u + 1 < TILES * NCH) {
            const int un = u + 1, tn = un >> 3, cn = un & 7;
            const float* g = Xb + (size_t)(cn * T1DC + dr) * NN
                           + (size_t)(tile_base + tn) * T1N + j * 4;
            #pragma unroll
            for (int r = 0; r < 8; ++r)
                R[r] = *(const float4*)(g + (size_t)(r * 8) * NN);
        }
        __syncthreads();

        #pragma unroll
        for (int ds4 = 0; ds4 < 4; ++ds4) {
            const int dl = half * 32 + ds4 * 8;
            const int dg = c * T1DC + dl;
            wmma::fragment<wmma::matrix_a, 16, 16, 8, wmma::precision::tf32, wmma::col_major> a0, a1;
            wmma::fragment<wmma::matrix_b, 16, 16, 8, wmma::precision::tf32, wmma::col_major> b0, b1;
            wmma::load_matrix_sync(a0, Xt + dl * X1LD + nc * 32,      X1LD);
            wmma::load_matrix_sync(a1, Xt + dl * X1LD + nc * 32 + 16, X1LD);
            wmma::load_matrix_sync(b0, Cs + dg,              C1LD);
            wmma::load_matrix_sync(b1, Cs + 16 * C1LD + dg,  C1LD);
            wmma::mma_sync(p00, a0, b0, p00);
            wmma::mma_sync(p01, a0, b1, p01);
            wmma::mma_sync(p10, a1, b0, p10);
            wmma::mma_sync(p11, a1, b1, p11);
        }

        if (c == NCH - 1) {
            const int tile = u >> 3;
            const int n0 = (tile_base + tile) * T1N;
            __syncthreads();

            *(float4*)&x2p[dr * X1LD + j * 4] = make_float4(xa, xb2, xc, xd2);
            float* dst = half ? As2 : As;
            wmma::store_matrix_sync(dst + (nc * 32) * AS1LD,           p00, AS1LD, wmma::mem_row_major);
            wmma::store_matrix_sync(dst + (nc * 32) * AS1LD + 16,      p01, AS1LD, wmma::mem_row_major);
            wmma::store_matrix_sync(dst + (nc * 32 + 16) * AS1LD,      p10, AS1LD, wmma::mem_row_major);
            wmma::store_matrix_sync(dst + (nc * 32 + 16) * AS1LD + 16, p11, AS1LD, wmma::mem_row_major);
            __syncthreads();

            {
                const int n = t >> 1, h = t & 1, ks = h * 16;
                float x2n = 0.f;
                #pragma unroll
                for (int r = 0; r < 8; ++r) x2n += x2p[r * X1LD + n];
                float sl[16];
                float m = -1e30f;
                #pragma unroll
                for (int jj = 0; jj < 16; ++jj) {
                    int k = ks + jj;
                    float xck = As[n * AS1LD + k] + As2[n * AS1LD + k];
                    float v = scs[k] * (x2n - 2.f * xck + c2s[k]);
                    sl[jj] = v; m = fmaxf(m, v);
                }
                m = fmaxf(m, __shfl_xor_sync(0xffffffffu, m, 1));
                float ssum = 0.f;
                #pragma unroll
                for (int jj = 0; jj < 16; ++jj) { sl[jj] = __expf(sl[jj] - m); ssum += sl[jj]; }
                ssum += __shfl_xor_sync(0xffffffffu, ssum, 1);
                const float inv = 1.0f / ssum;
                float4 o[4];
                #pragma unroll
                for (int jj = 0; jj < 16; ++jj)
                    ((float*)o)[jj] = wmma::__float_to_tf32(sl[jj] * inv);
                float4* dstA = (float4*)&A_buf[((size_t)b * NN + n0 + n) * KK + ks];
                dstA[0] = o[0]; dstA[1] = o[1]; dstA[2] = o[2]; dstA[3] = o[3];
            }
            __syncthreads();

            wmma::fill_fragment(p00, 0.f); wmma::fill_fragment(p01, 0.f);
            wmma::fill_fragment(p10, 0.f); wmma::fill_fragment(p11, 0.f);
            xa = xb2 = xc = xd2 = 0.f;
        }
    }
}

// ============================================================================
// Kernel 2: E[b,k,d] = sum_n A[b,n,k] * X[b,d,n]  -  S_k * c[k,d]
//   grid (16, 8, 4) d-quarters, 128 threads, 4 independent CTAs/SM
//   (barrier-decoupling experiment). Staging LDG.128 -> cvt -> STS.
// ============================================================================
#define T2N    32
#define CHUNK2 1024
#define NSUB2  (CHUNK2/T2N)   // 32
#define DQ     128            // d per CTA (quarter)
#define X2LD 36               // == 4 (mod 32)
#define X2F  (DQ*X2LD)        // 4608
#define A2LD 40               // == 8 (mod 32)
#define A2F  (T2N*A2LD)       // 1280
#define ES2LD 132
#define SM2_FLOATS (2*X2F + 2*A2F + 32)
#define SM2_BYTES  (SM2_FLOATS*4)     // 47,232 B -> 4 CTAs/SM

__global__ __launch_bounds__(128, 4)
void k2_aggregate(const float* __restrict__ X,
                  const float* __restrict__ CW,
                  float* __restrict__ out)
{
    extern __shared__ float sm[];
    float* Xs0 = sm;                // [128][36]
    float* Xs1 = Xs0 + X2F;
    float* As0 = Xs1 + X2F;         // [32][40]
    float* As1 = As0 + A2F;
    float* Ssm = As1 + A2F;         // [32]
    float* Es  = sm;                // epilogue reuse: [32][132] (4224 < 2*X2F)

    const int t = threadIdx.x;
    const int w = t >> 5;           // 0..3
    const int lane = t & 31;
    const int b = blockIdx.y;
    const int z = blockIdx.z;       // d-quarter
    const int nbase = blockIdx.x * CHUNK2;
    const float* Xb = X + (size_t)b * DD * NN + (size_t)z * DQ * NN;
    const float* Ab = A_buf + (size_t)b * NN * KK;

    // X staging map: jx = n-quad (0..7), dx = d-row in group of 16
    const int jx = t & 7;
    const int dx = t >> 3;          // 0..15
    const float* gx = Xb + (size_t)dx * NN + nbase + jx * 4;
    // A staging map: na = pixel row (0..31), ja = k-quad pair (0..3)
    const int na = t >> 2;
    const int ja = t & 3;

    if (t < 32) Ssm[t] = 0.f;

    // prefetch subtile 0
    float4 R[8];
    #pragma unroll
    for (int r = 0; r < 8; ++r)
        R[r] = *(const float4*)(gx + (size_t)(r * 16) * NN);
    float4 RA0 = *(const float4*)(Ab + (size_t)(nbase + na) * KK + ja * 4);
    float4 RA1 = *(const float4*)(Ab + (size_t)(nbase + na) * KK + (ja + 4) * 4);

    // persistent accumulators: warp w owns local d in [w*32, w*32+32), all 32 k
    wmma::fragment<wmma::accumulator, 16, 16, 8, float> eacc[2][2];
    #pragma unroll
    for (int kc = 0; kc < 2; ++kc)
        #pragma unroll
        for (int dt = 0; dt < 2; ++dt)
            wmma::fill_fragment(eacc[kc][dt], 0.f);

    float4 sacc0 = make_float4(0.f, 0.f, 0.f, 0.f);  // S_k partials, k=ja*4..
    float4 sacc1 = make_float4(0.f, 0.f, 0.f, 0.f);  // k=(ja+4)*4..

    for (int s = 0; s < NSUB2; ++s) {
        float* Xt = (s & 1) ? Xs1 : Xs0;
        float* At = (s & 1) ? As1 : As0;

        // consume registers: cvt X, STS both; accumulate S from A regs
        #pragma unroll
        for (int r = 0; r < 8; ++r) {
            float4 v = R[r];
            v.x = wmma::__float_to_tf32(v.x);
            v.y = wmma::__float_to_tf32(v.y);
            v.z = wmma::__float_to_tf32(v.z);
            v.w = wmma::__float_to_tf32(v.w);
            *(float4*)&Xt[(r * 16 + dx) * X2LD + jx * 4] = v;
        }
        *(float4*)&At[na * A2LD + ja * 4] = RA0;         // A already tf32
        *(float4*)&At[na * A2LD + (ja + 4) * 4] = RA1;
        sacc0.x += RA0.x; sacc0.y += RA0.y; sacc0.z += RA0.z; sacc0.w += RA0.w;
        sacc1.x += RA1.x; sacc1.y += RA1.y; sacc1.z += RA1.z; sacc1.w += RA1.w;

        // issue LDGs for next subtile
        if (s + 1 < NSUB2) {
            const int n1 = (s + 1) * T2N;
            const float* g = gx + n1;
            #pragma unroll
            for (int r = 0; r < 8; ++r)
                R[r] = *(const float4*)(g + (size_t)(r * 16) * NN);
            RA0 = *(const float4*)(Ab + (size_t)(nbase + n1 + na) * KK + ja * 4);
            RA1 = *(const float4*)(Ab + (size_t)(nbase + n1 + na) * KK + (ja + 4) * 4);
        }
        __syncthreads();

        // GEMM2: E[k][d] += sum_n A[n][k] * X[d][n]
        #pragma unroll
        for (int ns = 0; ns < 4; ++ns) {
            wmma::fragment<wmma::matrix_a, 16, 16, 8, wmma::precision::tf32, wmma::col_major> a2[2];
            wmma::load_matrix_sync(a2[0], At + ns * 8 * A2LD,      A2LD);
            wmma::load_matrix_sync(a2[1], At + ns * 8 * A2LD + 16, A2LD);
            #pragma unroll
            for (int dt = 0; dt < 2; ++dt) {
                wmma::fragment<wmma::matrix_b, 16, 16, 8, wmma::precision::tf32, wmma::col_major> b2;
                wmma::load_matrix_sync(b2, Xt + (w * 32 + dt * 16) * X2LD + ns * 8, X2LD);
                wmma::mma_sync(eacc[0][dt], a2[0], b2, eacc[0][dt]);
                wmma::mma_sync(eacc[1][dt], a2[1], b2, eacc[1][dt]);
            }
        }
        // single barrier per subtile: STS(s+1) targets the opposite buffer of
        // mma(s); mma(s-1) reads of that buffer completed before barrier(s).
    }
    __syncthreads();

    // fold S partials across na rows within warp (lanes sharing ja = l&3)
    #pragma unroll
    for (int m = 4; m <= 16; m <<= 1) {
        sacc0.x += __shfl_xor_sync(0xffffffffu, sacc0.x, m);
        sacc0.y += __shfl_xor_sync(0xffffffffu, sacc0.y, m);
        sacc0.z += __shfl_xor_sync(0xffffffffu, sacc0.z, m);
        sacc0.w += __shfl_xor_sync(0xffffffffu, sacc0.w, m);
        sacc1.x += __shfl_xor_sync(0xffffffffu, sacc1.x, m);
        sacc1.y += __shfl_xor_sync(0xffffffffu, sacc1.y, m);
        sacc1.z += __shfl_xor_sync(0xffffffffu, sacc1.z, m);
        sacc1.w += __shfl_xor_sync(0xffffffffu, sacc1.w, m);
    }
    if (lane < 4) {
        atomicAdd(&Ssm[ja * 4 + 0], sacc0.x);
        atomicAdd(&Ssm[ja * 4 + 1], sacc0.y);
        atomicAdd(&Ssm[ja * 4 + 2], sacc0.z);
        atomicAdd(&Ssm[ja * 4 + 3], sacc0.w);
        atomicAdd(&Ssm[(ja + 4) * 4 + 0], sacc1.x);
        atomicAdd(&Ssm[(ja + 4) * 4 + 1], sacc1.y);
        atomicAdd(&Ssm[(ja + 4) * 4 + 2], sacc1.z);
        atomicAdd(&Ssm[(ja + 4) * 4 + 3], sacc1.w);
    }
    // dump accumulators into Es
    #pragma unroll
    for (int kc = 0; kc < 2; ++kc)
        #pragma unroll
        for (int dt = 0; dt < 2; ++dt)
            wmma::store_matrix_sync(Es + kc * 16 * ES2LD + w * 32 + dt * 16,
                                    eacc[kc][dt], ES2LD, wmma::mem_row_major);
    __syncthreads();

    for (int i = t; i < KK * DQ; i += 128) {
        int k = i >> 7, dl = i & 127;
        int dglob = z * DQ + dl;
        float v = Es[k * ES2LD + dl] - Ssm[k] * CW[k * DD + dglob];
        atomicAdd(&out[(size_t)b * KK * DD + k * DD + dglob], v);
    }
}

// ============================================================================
extern "C" void kernel_launch(void* const* d_in, const int* in_sizes, int n_in,
                              void* d_out, int out_size) {
    (void)in_sizes; (void)n_in;
    const float* X     = (const float*)d_in[0];
    const float* CW    = (const float*)d_in[1];
    const float* scale = (const float*)d_in[2];
    float* out = (float*)d_out;

    cudaFuncSetAttribute(k1_assign,    cudaFuncAttributeMaxDynamicSharedMemorySize, SM1_BYTES);
    cudaFuncSetAttribute(k2_aggregate, cudaFuncAttributeMaxDynamicSharedMemorySize, SM2_BYTES);

    cudaMemsetAsync(d_out, 0, (size_t)out_size * sizeof(float));

    dim3 g1(NN / (T1N * TILES), BB);   // 16 x 8 = 128 CTAs (persistent, 4 tiles)
    k1_assign<<<g1, 512, SM1_BYTES>>>(X, CW, scale);

    dim3 g2(NN / CHUNK2, BB, 4);       // 16 x 8 x 4 = 512 CTAs (4 per SM)
    k2_aggregate<<<g2, 128, SM2_BYTES>>>(X, CW, out);
}

// round 10
// speedup vs baseline: 1.0218x; 1.0218x over previous
#include <cuda_runtime.h>
#include <mma.h>
#include <cstdint>

using namespace nvcuda;

#define BB 8
#define DD 512
#define KK 32
#define NN 16384

// 16 MB scratch for soft-assign matrix A[b][n][k] (tf32-rounded by K1)
__device__ float A_buf[(size_t)BB * NN * KK];

__device__ __forceinline__ void cp_async16(void* smem_dst, const void* gmem_src) {
    uint32_t s = (uint32_t)__cvta_generic_to_shared(smem_dst);
    asm volatile("cp.async.cg.shared.global [%0], [%1], 16;\n" :: "r"(s), "l"(gmem_src));
}
__device__ __forceinline__ void cp_commit() {
    asm volatile("cp.async.commit_group;\n" ::: "memory");
}
template<int N>
__device__ __forceinline__ void cp_wait() {
    asm volatile("cp.async.wait_group %0;\n" :: "n"(N) : "memory");
}

// ============================================================================
// Kernel 1: A = softmax_k( s_k * (||x||^2 - 2 x.c_k + ||c_k||^2) )
//   R7 version; only change: staging stores RAW X (HMMA truncates tf32).
// ============================================================================
#define T1N   256
#define T1DC  64
#define NCH   (DD/T1DC)       // 8
#define TILES 4
#define X1LD 264
#define X1F  (T1DC*X1LD)
#define C1LD 516
#define C1F  (KK*C1LD)
#define AS1LD 36
#define SM1_FLOATS (2*X1F + C1F + 64)
#define SM1_BYTES  (SM1_FLOATS*4)

__global__ __launch_bounds__(512, 1)
void k1_assign(const float* __restrict__ X,
               const float* __restrict__ CW,
               const float* __restrict__ scale)
{
    extern __shared__ float sm[];
    float* Xs0 = sm;
    float* Xs1 = Xs0 + X1F;
    float* Cs  = Xs1 + X1F;
    float* c2s = Cs + C1F;
    float* scs = c2s + 32;
    float* As  = Xs0;
    float* As2 = Xs1;
    float* x2p = Xs1 + 9216;

    const int t = threadIdx.x;
    const int w = t >> 5;
    const int b = blockIdx.y;
    const int tile_base = blockIdx.x * TILES;
    const float* Xb = X + (size_t)b * DD * NN;

    const int j  = t & 63;
    const int dr = t >> 6;
    const int nc = w & 7, half = w >> 3;

    float4 R[8];
    {
        const float* g = Xb + (size_t)dr * NN + tile_base * T1N + j * 4;
        #pragma unroll
        for (int r = 0; r < 8; ++r)
            R[r] = *(const float4*)(g + (size_t)(r * 8) * NN);
    }

    for (int i = t; i < KK * DD; i += 512) {
        int k = i >> 9, d = i & 511;
        Cs[k * C1LD + d] = wmma::__float_to_tf32(CW[i]);
    }
    if (t < 32) scs[t] = scale[t];
    __syncthreads();
    if (t < 32) {
        float s = 0.f;
        #pragma unroll 8
        for (int d = 0; d < DD; ++d) { float v = Cs[t * C1LD + d]; s += v * v; }
        c2s[t] = s;
    }

    wmma::fragment<wmma::accumulator, 16, 16, 8, float> p00, p01, p10, p11;
    wmma::fill_fragment(p00, 0.f); wmma::fill_fragment(p01, 0.f);
    wmma::fill_fragment(p10, 0.f); wmma::fill_fragment(p11, 0.f);
    float xa = 0.f, xb2 = 0.f, xc = 0.f, xd2 = 0.f;

    for (int u = 0; u < TILES * NCH; ++u) {
        const int c = u & 7;
        float* Xt = (u & 1) ? Xs1 : Xs0;

        // consume R: x^2, STS raw (NO cvt — tf32 mma truncates)
        #pragma unroll
        for (int r = 0; r < 8; ++r) {
            float4 v = R[r];
            xa += v.x * v.x; xb2 += v.y * v.y; xc += v.z * v.z; xd2 += v.w * v.w;
            *(float4*)&Xt[(r * 8 + dr) * X1LD + j * 4] = v;
        }
        if (u + 1 < TILES * NCH) {
            const int un = u + 1, tn = un >> 3, cn = un & 7;
            const float* g = Xb + (size_t)(cn * T1DC + dr) * NN
                           + (size_t)(tile_base + tn) * T1N + j * 4;
            #pragma unroll
            for (int r = 0; r < 8; ++r)
                R[r] = *(const float4*)(g + (size_t)(r * 8) * NN);
        }
        __syncthreads();

        #pragma unroll
        for (int ds4 = 0; ds4 < 4; ++ds4) {
            const int dl = half * 32 + ds4 * 8;
            const int dg = c * T1DC + dl;
            wmma::fragment<wmma::matrix_a, 16, 16, 8, wmma::precision::tf32, wmma::col_major> a0, a1;
            wmma::fragment<wmma::matrix_b, 16, 16, 8, wmma::precision::tf32, wmma::col_major> b0, b1;
            wmma::load_matrix_sync(a0, Xt + dl * X1LD + nc * 32,      X1LD);
            wmma::load_matrix_sync(a1, Xt + dl * X1LD + nc * 32 + 16, X1LD);
            wmma::load_matrix_sync(b0, Cs + dg,              C1LD);
            wmma::load_matrix_sync(b1, Cs + 16 * C1LD + dg,  C1LD);
            wmma::mma_sync(p00, a0, b0, p00);
            wmma::mma_sync(p01, a0, b1, p01);
            wmma::mma_sync(p10, a1, b0, p10);
            wmma::mma_sync(p11, a1, b1, p11);
        }

        if (c == NCH - 1) {
            const int tile = u >> 3;
            const int n0 = (tile_base + tile) * T1N;
            __syncthreads();

            *(float4*)&x2p[dr * X1LD + j * 4] = make_float4(xa, xb2, xc, xd2);
            float* dst = half ? As2 : As;
            wmma::store_matrix_sync(dst + (nc * 32) * AS1LD,           p00, AS1LD, wmma::mem_row_major);
            wmma::store_matrix_sync(dst + (nc * 32) * AS1LD + 16,      p01, AS1LD, wmma::mem_row_major);
            wmma::store_matrix_sync(dst + (nc * 32 + 16) * AS1LD,      p10, AS1LD, wmma::mem_row_major);
            wmma::store_matrix_sync(dst + (nc * 32 + 16) * AS1LD + 16, p11, AS1LD, wmma::mem_row_major);
            __syncthreads();

            {
                const int n = t >> 1, h = t & 1, ks = h * 16;
                float x2n = 0.f;
                #pragma unroll
                for (int r = 0; r < 8; ++r) x2n += x2p[r * X1LD + n];
                float sl[16];
                float m = -1e30f;
                #pragma unroll
                for (int jj = 0; jj < 16; ++jj) {
                    int k = ks + jj;
                    float xck = As[n * AS1LD + k] + As2[n * AS1LD + k];
                    float v = scs[k] * (x2n - 2.f * xck + c2s[k]);
                    sl[jj] = v; m = fmaxf(m, v);
                }
                m = fmaxf(m, __shfl_xor_sync(0xffffffffu, m, 1));
                float ssum = 0.f;
                #pragma unroll
                for (int jj = 0; jj < 16; ++jj) { sl[jj] = __expf(sl[jj] - m); ssum += sl[jj]; }
                ssum += __shfl_xor_sync(0xffffffffu, ssum, 1);
                const float inv = 1.0f / ssum;
                float4 o[4];
                #pragma unroll
                for (int jj = 0; jj < 16; ++jj)
                    ((float*)o)[jj] = wmma::__float_to_tf32(sl[jj] * inv);
                float4* dstA = (float4*)&A_buf[((size_t)b * NN + n0 + n) * KK + ks];
                dstA[0] = o[0]; dstA[1] = o[1]; dstA[2] = o[2]; dstA[3] = o[3];
            }
            __syncthreads();

            wmma::fill_fragment(p00, 0.f); wmma::fill_fragment(p01, 0.f);
            wmma::fill_fragment(p10, 0.f); wmma::fill_fragment(p11, 0.f);
            xa = xb2 = xc = xd2 = 0.f;
        }
    }
}

// ============================================================================
// Kernel 2: E[b,k,d] = sum_n A[b,n,k] * X[b,d,n]  -  S_k * c[k,d]
//   grid (16, 8, 2) d-halves, 128 threads, 2 CTAs/SM.
//   cp.async staging (raw X — tf32 truncation), 4 warps x 64d, no cvt anywhere.
// ============================================================================
#define T2N    32
#define CHUNK2 1024
#define NSUB2  (CHUNK2/T2N)   // 32
#define DH     256            // d per CTA
#define X2LD 36               // == 4 (mod 32): conflict-free matrix_b loads
#define X2F  (DH*X2LD)        // 9216
#define A2LD 40               // == 8 (mod 32): conflict-free matrix_a loads
#define A2F  (T2N*A2LD)       // 1280
#define ES2LD 260
#define SM2_FLOATS (2*X2F + 2*A2F + 32)
#define SM2_BYTES  (SM2_FLOATS*4)     // 84,096 B -> 2 CTAs/SM

__global__ __launch_bounds__(128, 2)
void k2_aggregate(const float* __restrict__ X,
                  const float* __restrict__ CW,
                  float* __restrict__ out)
{
    extern __shared__ float sm[];
    float* Xs0 = sm;                // [256][36]
    float* Xs1 = Xs0 + X2F;
    float* As0 = Xs1 + X2F;         // [32][40]
    float* As1 = As0 + A2F;
    float* Ssm = As1 + A2F;         // [32]
    float* Es  = sm;                // epilogue reuse: [32][260] = 8320 < 2*X2F

    const int t = threadIdx.x;
    const int w = t >> 5;           // 0..3
    const int lane = t & 31;
    const int b = blockIdx.y;
    const int z = blockIdx.z;       // d-half
    const int nbase = blockIdx.x * CHUNK2;
    const float* Xb = X + (size_t)b * DD * NN + (size_t)z * DH * NN;
    const float* Ab = A_buf + (size_t)b * NN * KK;

    // X staging map: jx = n-quad (0..7), dxr = d-row in group of 16
    const int jx = t & 7;
    const int dxr = t >> 3;         // 0..15
    // A staging map: na = pixel row (0..31), jaq = k-quad (0..3); 2 quads each
    const int na = t >> 2;
    const int jaq = t & 3;

    // ---- stage helper (one commit group per subtile) ----
    auto stage = [&](int s) {
        const int n0 = nbase + s * T2N;
        float* xd = (s & 1) ? Xs1 : Xs0;
        float* ad = (s & 1) ? As1 : As0;
        const float* gx = Xb + n0 + jx * 4;
        #pragma unroll
        for (int r = 0; r < 16; ++r) {
            int d = r * 16 + dxr;
            cp_async16(&xd[d * X2LD + jx * 4], gx + (size_t)d * NN);
        }
        const float* ga = Ab + (size_t)(n0 + na) * KK;
        cp_async16(&ad[na * A2LD + jaq * 4],       ga + jaq * 4);
        cp_async16(&ad[na * A2LD + (jaq + 4) * 4], ga + (jaq + 4) * 4);
        cp_commit();
    };

    // persistent accumulators: warp w owns local d in [w*64, w*64+64), all 32 k
    wmma::fragment<wmma::accumulator, 16, 16, 8, float> eacc[2][4];
    #pragma unroll
    for (int kc = 0; kc < 2; ++kc)
        #pragma unroll
        for (int dt = 0; dt < 4; ++dt)
            wmma::fill_fragment(eacc[kc][dt], 0.f);

    float sreg = 0.f;   // warp 0 lane k: running S_k

    stage(0);
    stage(1);

    for (int s = 0; s < NSUB2; ++s) {
        if (s + 1 < NSUB2) cp_wait<1>(); else cp_wait<0>();
        __syncthreads();                       // tiles for subtile s visible

        float* Xt = (s & 1) ? Xs1 : Xs0;
        float* At = (s & 1) ? As1 : As0;

        // warp 0: S_k += column sums of At (conflict-free: A2LD==8 mod 32)
        if (w == 0) {
            float acc = 0.f;
            #pragma unroll
            for (int n = 0; n < T2N; ++n) acc += At[n * A2LD + lane];
            sreg += acc;
        }

        // GEMM2: E[k][d] += sum_n A[n][k] * X[d][n]  (raw X: HW-truncated tf32)
        #pragma unroll
        for (int ns = 0; ns < 4; ++ns) {
            wmma::fragment<wmma::matrix_a, 16, 16, 8, wmma::precision::tf32, wmma::col_major> a2[2];
            wmma::load_matrix_sync(a2[0], At + ns * 8 * A2LD,      A2LD);
            wmma::load_matrix_sync(a2[1], At + ns * 8 * A2LD + 16, A2LD);
            #pragma unroll
            for (int dt = 0; dt < 4; ++dt) {
                wmma::fragment<wmma::matrix_b, 16, 16, 8, wmma::precision::tf32, wmma::col_major> b2;
                wmma::load_matrix_sync(b2, Xt + (w * 64 + dt * 16) * X2LD + ns * 8, X2LD);
                wmma::mma_sync(eacc[0][dt], a2[0], b2, eacc[0][dt]);
                wmma::mma_sync(eacc[1][dt], a2[1], b2, eacc[1][dt]);
            }
        }
        __syncthreads();                       // all reads of buffer s done
        if (s + 2 < NSUB2) stage(s + 2);       // refill the freed buffer
    }

    if (w == 0) Ssm[lane] = sreg;
    // dump accumulators into Es (X buffers dead)
    #pragma unroll
    for (int kc = 0; kc < 2; ++kc)
        #pragma unroll
        for (int dt = 0; dt < 4; ++dt)
            wmma::store_matrix_sync(Es + kc * 16 * ES2LD + w * 64 + dt * 16,
                                    eacc[kc][dt], ES2LD, wmma::mem_row_major);
    __syncthreads();

    for (int i = t; i < KK * DH; i += 128) {
        int k = i >> 8, dl = i & 255;
        int dglob = z * DH + dl;
        float v = Es[k * ES2LD + dl] - Ssm[k] * CW[k * DD + dglob];
        atomicAdd(&out[(size_t)b * KK * DD + k * DD + dglob], v);
    }
}

// ============================================================================
extern "C" void kernel_launch(void* const* d_in, const int* in_sizes, int n_in,
                              void* d_out, int out_size) {
    (void)in_sizes; (void)n_in;
    const float* X     = (const float*)d_in[0];
    const float* CW    = (const float*)d_in[1];
    const float* scale = (const float*)d_in[2];
    float* out = (float*)d_out;

    cudaFuncSetAttribute(k1_assign,    cudaFuncAttributeMaxDynamicSharedMemorySize, SM1_BYTES);
    cudaFuncSetAttribute(k2_aggregate, cudaFuncAttributeMaxDynamicSharedMemorySize, SM2_BYTES);

    cudaMemsetAsync(d_out, 0, (size_t)out_size * sizeof(float));

    dim3 g1(NN / (T1N * TILES), BB);   // 16 x 8 = 128 CTAs (persistent, 4 tiles)
    k1_assign<<<g1, 512, SM1_BYTES>>>(X, CW, scale);

    dim3 g2(NN / CHUNK2, BB, 2);       // 16 x 8 x 2 = 256 CTAs (2 per SM)
    k2_aggregate<<<g2, 128, SM2_BYTES>>>(X, CW, out);
}